// round 4
// baseline (speedup 1.0000x reference)
#include <cuda_runtime.h>
#include <cuda_bf16.h>
#include <stdint.h>

// Problem constants (fixed by reference: B=16, NT=4096, D=512, V=2545)
#define B_  16
#define NT_ 4096
#define D_  512
#define V_  2545
#define D_VEC (D_ / 4)          // 128 float4 per embedding row
#define NROWS (B_ * NT_)        // 65536 output rows

// Scratch (device allocations forbidden -> __device__ globals)
__device__ int g_len[B_];
__device__ int g_is64;

// ---------------------------------------------------------------------------
// Prep-lite: one block per batch row (16 blocks, 512 threads).
//  (a) probe text dtype layout: interpret first 256 int32-word pairs as
//      little-endian int64; all must have hi == sign_ext(lo) and lo in
//      [-1, V). Random int32 token data defeats this w.p. ~0.
//  (b) count valid tokens L_b (token >= 0) under the detected layout.
// No mapping work here — that moved into the embed kernel.
// ---------------------------------------------------------------------------
__global__ void __launch_bounds__(512)
prep_kernel(const int* __restrict__ t32) {
    const int b = blockIdx.x;

    int bad = 0;
    for (int k = threadIdx.x; k < 256; k += blockDim.x) {
        const int lo = t32[2 * k];
        const int hi = t32[2 * k + 1];
        const int want_hi = (lo < 0) ? -1 : 0;
        if (hi != want_hi || lo < -1 || lo >= V_) bad = 1;
    }
    const int is64 = __syncthreads_or(bad) ? 0 : 1;
    const int stride = is64 ? 2 : 1;

    const int* row = t32 + (size_t)b * NT_ * stride;
    int cnt = 0;
    #pragma unroll
    for (int i = threadIdx.x; i < NT_; i += 512)
        cnt += (row[i * stride] >= 0);

    #pragma unroll
    for (int off = 16; off > 0; off >>= 1)
        cnt += __shfl_down_sync(0xFFFFFFFFu, cnt, off);

    __shared__ int s_part[16];
    const int wid = threadIdx.x >> 5;
    if ((threadIdx.x & 31) == 0) s_part[wid] = cnt;
    __syncthreads();
    if (threadIdx.x == 0) {
        int total = 0;
        for (int w = 0; w < 16; ++w) total += s_part[w];
        g_len[b] = total;
        if (b == 0) g_is64 = is64;
    }
}

// ---------------------------------------------------------------------------
// Embed kernel: inline stretch mapping + gather-copy, MLP=8 with dedup.
// 256 threads/block = 2 groups of 128 lanes; each group copies 8 CONSECUTIVE
// output rows (16 rows/block). Consecutive rows frequently map to the same
// source token (base = 4096/L repeats), so duplicate emb loads are replaced
// by register copies — cuts L2 read traffic.
// grid = NROWS/16 = 4096 blocks.
// ---------------------------------------------------------------------------
__global__ void __launch_bounds__(256)
embed_kernel(const int* __restrict__ t32,
             const float4* __restrict__ emb,
             float4* __restrict__ out) {
    const int lane = threadIdx.x & 127;
    const int sub  = threadIdx.x >> 7;                  // 0 or 1
    const int b    = blockIdx.x >> 8;                   // 256 blocks per batch
    const int p0   = ((blockIdx.x & 255) << 4) + (sub << 3);

    float4* dst = out + ((size_t)b * NT_ + p0) * D_VEC + lane;

    const int L = g_len[b];
    if (L <= 0) {
        const float4 z = make_float4(0.f, 0.f, 0.f, 0.f);
        #pragma unroll
        for (int k = 0; k < 8; ++k) __stcs(dst + (size_t)k * D_VEC, z);
        return;
    }

    const int stride = g_is64 ? 2 : 1;
    const int* row = t32 + (size_t)b * NT_ * stride;

    const unsigned base = (unsigned)NT_ / (unsigned)L;
    const unsigned rem  = (unsigned)NT_ % (unsigned)L;
    const unsigned boundary = ((unsigned)L - rem) * base;

    int tok[8];
    #pragma unroll
    for (int k = 0; k < 8; ++k) {
        const unsigned p = (unsigned)(p0 + k);
        unsigned j;
        if (p < boundary) j = p / base;
        else              j = ((unsigned)L - rem) + (p - boundary) / (base + 1);
        int t = row[j * stride] + 1;                    // in [1, V] for valid prefix
        tok[k] = min(max(t, 0), V_);                    // hard safety clamp
    }

    float4 v[8];
    #pragma unroll
    for (int k = 0; k < 8; ++k) {
        if (k == 0 || tok[k] != tok[k - 1])
            v[k] = __ldg(emb + (size_t)tok[k] * D_VEC + lane);
        else
            v[k] = v[k - 1];
    }

    #pragma unroll
    for (int k = 0; k < 8; ++k)
        __stcs(dst + (size_t)k * D_VEC, v[k]);
}

// ---------------------------------------------------------------------------
// Launch. Identify inputs by element count:
//   text: 65536 elements (int32 OR int64-elements) or 131072 int32-words;
//         the device-side probe resolves the actual layout.
//   emb : (2545+1)*512 = 1303552 fp32.
// ---------------------------------------------------------------------------
extern "C" void kernel_launch(void* const* d_in, const int* in_sizes, int n_in,
                              void* d_out, int out_size) {
    const int*   text = nullptr;
    const float* emb  = nullptr;
    for (int i = 0; i < n_in; ++i) {
        if (in_sizes[i] == NROWS || in_sizes[i] == 2 * NROWS)
            text = (const int*)d_in[i];
        else if (in_sizes[i] == (V_ + 1) * D_)
            emb = (const float*)d_in[i];
    }

    prep_kernel<<<B_, 512>>>(text);
    embed_kernel<<<NROWS / 16, 256>>>(text, (const float4*)emb, (float4*)d_out);
    (void)out_size;
}

// round 6
// speedup vs baseline: 1.0555x; 1.0555x over previous
#include <cuda_runtime.h>
#include <cuda_bf16.h>
#include <stdint.h>

// Problem constants (fixed by reference: B=16, NT=4096, D=512, V=2545)
#define B_  16
#define NT_ 4096
#define D_  512
#define V_  2545
#define D_VEC (D_ / 4)          // 128 float4 per embedding row
#define NROWS (B_ * NT_)        // 65536 output rows

// Scratch (device allocations forbidden -> __device__ global)
__device__ int g_tok[NROWS];    // source token per output row (+1 applied), or -1 => zeros

// ---------------------------------------------------------------------------
// Prep kernel: one block per batch row b (16 blocks, 512 threads).
//  (a) dtype probe: interpret first 256 int32-word pairs as little-endian
//      int64 (hi == sign_ext(lo), lo in [-1, V)) => int64 layout; else int32.
//  (b) count valid tokens L_b (token >= 0) — simple, proven reduction.
//  (c) stretch mapping j(p) for all p in [0,4096) -> g_tok[b*4096+p].
// ---------------------------------------------------------------------------
__global__ void __launch_bounds__(512)
prep_kernel(const int* __restrict__ t32) {
    const int b = blockIdx.x;
    const int tid = threadIdx.x;

    // --- dtype probe ---
    int bad = 0;
    for (int k = tid; k < 256; k += 512) {
        const int lo = t32[2 * k];
        const int hi = t32[2 * k + 1];
        const int want_hi = (lo < 0) ? -1 : 0;
        if (hi != want_hi || lo < -1 || lo >= V_) bad = 1;
    }
    const int is64 = __syncthreads_or(bad) ? 0 : 1;
    const int stride = is64 ? 2 : 1;
    const int* row = t32 + (size_t)b * NT_ * stride;

    // --- count valid tokens (valid = token >= 0) ---
    int cnt = 0;
    #pragma unroll
    for (int i = tid; i < NT_; i += 512)
        cnt += (row[(size_t)i * stride] >= 0);

    #pragma unroll
    for (int off = 16; off > 0; off >>= 1)
        cnt += __shfl_down_sync(0xFFFFFFFFu, cnt, off);

    __shared__ int s_part[16];
    if ((tid & 31) == 0) s_part[tid >> 5] = cnt;
    __syncthreads();
    __shared__ int s_L;
    if (tid == 0) {
        int total = 0;
        for (int w = 0; w < 16; ++w) total += s_part[w];
        s_L = total;
    }
    __syncthreads();
    const int L = s_L;

    // --- stretch mapping -> g_tok ---
    int* tok_row = g_tok + b * NT_;
    if (L <= 0) {
        for (int p = tid; p < NT_; p += 512) tok_row[p] = -1;
        return;
    }
    const unsigned base = (unsigned)NT_ / (unsigned)L;
    const unsigned rem  = (unsigned)NT_ % (unsigned)L;
    const unsigned boundary = ((unsigned)L - rem) * base;

    #pragma unroll
    for (int p = tid; p < NT_; p += 512) {
        unsigned j;
        if ((unsigned)p < boundary) j = (unsigned)p / base;
        else                        j = ((unsigned)L - rem) + ((unsigned)p - boundary) / (base + 1);
        int t = row[(size_t)j * stride] + 1;   // in [1, V] for valid prefix
        tok_row[p] = min(max(t, 0), V_);       // hard safety clamp
    }
}

// ---------------------------------------------------------------------------
// Embed kernel: pure gather-copy, MLP=8, consecutive-duplicate dedup.
// 256 threads/block = 2 groups of 128 lanes; each group copies 8 CONSECUTIVE
// output rows (block covers 16). Adjacent output rows often map to the same
// source token (stretch factor = 4096/L >= 2 whenever L <= 2048), so
// duplicate emb loads become register copies — cutting L2 read traffic,
// which the R3 numbers show is the binding resource (~6300 B/cyc LTS cap).
// grid = NROWS/16 = 4096 blocks.
// ---------------------------------------------------------------------------
__global__ void __launch_bounds__(256)
embed_copy_kernel(const float4* __restrict__ emb,
                  float4* __restrict__ out) {
    const int lane = threadIdx.x & 127;
    const int sub  = threadIdx.x >> 7;                 // 0 or 1
    const int rowBase = blockIdx.x * 16 + sub * 8;     // 8 consecutive rows per group

    int tok[8];
    #pragma unroll
    for (int k = 0; k < 8; ++k)
        tok[k] = __ldg(&g_tok[rowBase + k]);

    float4* dst = out + (size_t)rowBase * D_VEC + lane;

    float4 v[8];
    #pragma unroll
    for (int k = 0; k < 8; ++k) {
        if (k > 0 && tok[k] == tok[k - 1]) {
            v[k] = v[k - 1];
        } else if (tok[k] >= 0) {
            v[k] = __ldg(emb + (size_t)tok[k] * D_VEC + lane);
        } else {
            v[k] = make_float4(0.f, 0.f, 0.f, 0.f);
        }
    }

    #pragma unroll
    for (int k = 0; k < 8; ++k)
        __stcs(dst + (size_t)k * D_VEC, v[k]);
}

// ---------------------------------------------------------------------------
// Launch. Identify inputs by element count:
//   text: 65536 elements (int32 or int64) or 131072 int32-words; the
//         device-side probe resolves the layout.
//   emb : (2545+1)*512 = 1303552 fp32.
// ---------------------------------------------------------------------------
extern "C" void kernel_launch(void* const* d_in, const int* in_sizes, int n_in,
                              void* d_out, int out_size) {
    const int*   text = nullptr;
    const float* emb  = nullptr;
    for (int i = 0; i < n_in; ++i) {
        if (in_sizes[i] == NROWS || in_sizes[i] == 2 * NROWS)
            text = (const int*)d_in[i];
        else if (in_sizes[i] == (V_ + 1) * D_)
            emb = (const float*)d_in[i];
    }

    prep_kernel<<<B_, 512>>>(text);
    embed_copy_kernel<<<NROWS / 16, 256>>>((const float4*)emb, (float4*)d_out);
    (void)out_size;
}

// round 7
// speedup vs baseline: 1.1302x; 1.0708x over previous
#include <cuda_runtime.h>
#include <cuda_bf16.h>
#include <stdint.h>

// Problem constants (fixed by reference: B=16, NT=4096, D=512, V=2545)
#define B_  16
#define NT_ 4096
#define D_  512
#define V_  2545
#define D_VEC (D_ / 4)          // 128 float4 per embedding row
#define NROWS (B_ * NT_)        // 65536 output rows
#define CHUNKS_PER_B 8          // prep blocks per batch row
#define CHUNK (NT_ / CHUNKS_PER_B)   // 512 positions per prep block

// Scratch (device allocations forbidden -> __device__ global)
__device__ int g_tok[NROWS];    // source token per output row (+1 applied), or -1 => zeros

// ---------------------------------------------------------------------------
// Prep kernel: 128 blocks = 8 chunks x 16 batches, 512 threads each.
// Every block independently:
//  (a) probes text dtype layout (int64 little-endian words vs int32) from the
//      first 256 word-pairs — always in bounds, deterministic;
//  (b) counts valid tokens L_b of its batch row (redundant across the 8
//      chunk-blocks of a batch; 4096 L2-resident reads — cheap);
//  (c) computes the stretch mapping for its 512 positions -> g_tok.
// Serial mapping depth per thread = 1 (was 8), so the kernel is one short
// latency chain instead of a long one.
// ---------------------------------------------------------------------------
__global__ void __launch_bounds__(512)
prep_kernel(const int* __restrict__ t32) {
    const int b     = blockIdx.x >> 3;          // batch row
    const int chunk = blockIdx.x & 7;           // which 512-position slice
    const int tid   = threadIdx.x;

    // --- dtype probe ---
    int bad = 0;
    for (int k = tid; k < 256; k += 512) {
        const int lo = t32[2 * k];
        const int hi = t32[2 * k + 1];
        const int want_hi = (lo < 0) ? -1 : 0;
        if (hi != want_hi || lo < -1 || lo >= V_) bad = 1;
    }
    const int is64 = __syncthreads_or(bad) ? 0 : 1;
    const int stride = is64 ? 2 : 1;
    const int* row = t32 + (size_t)b * NT_ * stride;

    // --- count valid tokens (valid = token >= 0) ---
    int cnt = 0;
    #pragma unroll
    for (int i = tid; i < NT_; i += 512)
        cnt += (row[(size_t)i * stride] >= 0);

    #pragma unroll
    for (int off = 16; off > 0; off >>= 1)
        cnt += __shfl_down_sync(0xFFFFFFFFu, cnt, off);

    __shared__ int s_part[16];
    if ((tid & 31) == 0) s_part[tid >> 5] = cnt;
    __syncthreads();
    __shared__ int s_L;
    if (tid == 0) {
        int total = 0;
        for (int w = 0; w < 16; ++w) total += s_part[w];
        s_L = total;
    }
    __syncthreads();
    const int L = s_L;

    // --- stretch mapping for this block's 512 positions ---
    const int p = chunk * CHUNK + tid;          // one position per thread
    int* tok_row = g_tok + b * NT_;

    if (L <= 0) {
        tok_row[p] = -1;
        return;
    }
    const unsigned base = (unsigned)NT_ / (unsigned)L;
    const unsigned rem  = (unsigned)NT_ % (unsigned)L;
    const unsigned boundary = ((unsigned)L - rem) * base;

    unsigned j;
    if ((unsigned)p < boundary) j = (unsigned)p / base;
    else                        j = ((unsigned)L - rem) + ((unsigned)p - boundary) / (base + 1);
    int t = row[(size_t)j * stride] + 1;        // in [1, V] for valid prefix
    tok_row[p] = min(max(t, 0), V_);            // hard safety clamp
}

// ---------------------------------------------------------------------------
// Embed kernel: pure gather-copy, proven R3 configuration.
// 256 threads/block handle 8 rows: thread t owns lane = t & 127 of rows
// rowBase + (t>>7) + {0,2,4,6}. Four independent float4 loads issued
// back-to-back (MLP=4), then four streaming stores.
// grid = NROWS / 8 = 8192 blocks.
// ---------------------------------------------------------------------------
__global__ void __launch_bounds__(256)
embed_copy_kernel(const float4* __restrict__ emb,
                  float4* __restrict__ out) {
    const int lane = threadIdx.x & 127;
    const int sub  = threadIdx.x >> 7;          // 0 or 1
    const int rowBase = blockIdx.x * 8 + sub;

    int tok[4];
    #pragma unroll
    for (int k = 0; k < 4; ++k)
        tok[k] = __ldg(&g_tok[rowBase + 2 * k]);

    float4 v[4];
    #pragma unroll
    for (int k = 0; k < 4; ++k) {
        if (tok[k] >= 0)
            v[k] = __ldg(emb + (size_t)tok[k] * D_VEC + lane);
        else
            v[k] = make_float4(0.f, 0.f, 0.f, 0.f);
    }

    #pragma unroll
    for (int k = 0; k < 4; ++k)
        __stcs(out + (size_t)(rowBase + 2 * k) * D_VEC + lane, v[k]);
}

// ---------------------------------------------------------------------------
// Launch. Identify inputs by element count:
//   text: 65536 elements (int32 or int64) or 131072 int32-words; the
//         device-side probe resolves the layout.
//   emb : (2545+1)*512 = 1303552 fp32.
// ---------------------------------------------------------------------------
extern "C" void kernel_launch(void* const* d_in, const int* in_sizes, int n_in,
                              void* d_out, int out_size) {
    const int*   text = nullptr;
    const float* emb  = nullptr;
    for (int i = 0; i < n_in; ++i) {
        if (in_sizes[i] == NROWS || in_sizes[i] == 2 * NROWS)
            text = (const int*)d_in[i];
        else if (in_sizes[i] == (V_ + 1) * D_)
            emb = (const float*)d_in[i];
    }

    prep_kernel<<<B_ * CHUNKS_PER_B, 512>>>(text);
    embed_copy_kernel<<<NROWS / 8, 256>>>((const float4*)emb, (float4*)d_out);
    (void)out_size;
}